// round 1
// baseline (speedup 1.0000x reference)
#include <cuda_runtime.h>
#include <cstdint>

// Problem constants
#define Bx 256
#define Tx 3000
#define Ix 40
#define Hx 64
#define Gx 256        // 4*H gates
#define CHUNK 120     // T % CHUNK == 0 (3000/120 = 25 chunks)

// Scratch for per-timestep hidden states (allocation-free rule: __device__ globals)
__device__ float g_hf[(size_t)Bx * Tx * Hx];
__device__ float g_hb[(size_t)Bx * Tx * Hx];

// ---------- packed f32x2 FMA (FFMA2) ----------
union F2U { float2 f; unsigned long long u; };

__device__ __forceinline__ void ffma2(unsigned long long& acc,
                                      unsigned long long a,
                                      unsigned long long b) {
    asm("fma.rn.f32x2 %0, %1, %2, %0;" : "+l"(acc) : "l"(a), "l"(b));
}

__device__ __forceinline__ float fsigmoid(float x) {
    // 1/(1+e^-x); __expf overflow -> inf -> fdividef -> 0 (correct saturation)
    return __fdividef(1.0f, 1.0f + __expf(-x));
}
__device__ __forceinline__ float ftanh_fast(float x) {
    // 1 - 2/(e^{2x}+1); saturates correctly at +/-inf exp
    return 1.0f - __fdividef(2.0f, __expf(2.0f * x) + 1.0f);
}

// ================= LSTM kernel =================
// grid = 512 blocks (one per (batch, direction)), block = 512 threads.
// thread t: gate g = t>>1, K-half = t&1.
//   half 0: h[0:32), x[0:20)   half 1: h[32:64), x[20:40)
__global__ __launch_bounds__(512, 1)
void lstm_kernel(const float* __restrict__ x,
                 const float* __restrict__ Wih_f, const float* __restrict__ Whh_f,
                 const float* __restrict__ bih_f, const float* __restrict__ bhh_f,
                 const float* __restrict__ Wih_b, const float* __restrict__ Whh_b,
                 const float* __restrict__ bih_b, const float* __restrict__ bhh_b)
{
    const int blk = blockIdx.x;       // 0..511
    const int b   = blk >> 1;
    const int dir = blk & 1;

    const float* Wih = dir ? Wih_b : Wih_f;
    const float* Whh = dir ? Whh_b : Whh_f;
    const float* bih = dir ? bih_b : bih_f;
    const float* bhh = dir ? bhh_b : bhh_f;
    float* hout = dir ? g_hb : g_hf;

    const int tid  = threadIdx.x;
    const int g    = tid >> 1;
    const int half = tid & 1;

    __shared__ __align__(16) float sx[CHUNK * Ix];   // 19.2 KB x staging
    __shared__ __align__(16) float sh[Hx];           // h state
    __shared__ float sgates[Gx];                     // activated gates

    // ---- load this thread's weight half-rows into registers (f32x2) ----
    unsigned long long wih[10];  // 20 floats
    unsigned long long whh[16];  // 32 floats
    {
        const float2* wi = (const float2*)(Wih + (size_t)g * Ix + half * 20);
        const float2* wh = (const float2*)(Whh + (size_t)g * Hx + half * 32);
        #pragma unroll
        for (int j = 0; j < 10; j++) { F2U u; u.f = wi[j]; wih[j] = u.u; }
        #pragma unroll
        for (int j = 0; j < 16; j++) { F2U u; u.f = wh[j]; whh[j] = u.u; }
    }
    const float bias_g = bih[g] + bhh[g];
    const int region = g >> 6;   // 0:i 1:f 2:g 3:o  (uniform per warp)

    // init h = 0
    if (tid < Hx) sh[tid] = 0.0f;
    float cstate = 0.0f;
    __syncthreads();

    for (int s0 = 0; s0 < Tx; s0 += CHUNK) {
        // stage x chunk: absolute timesteps [tbase, tbase+CHUNK)
        const int tbase = dir ? (Tx - CHUNK - s0) : s0;
        {
            const float4* xs = (const float4*)(x + ((size_t)b * Tx + tbase) * Ix);
            float4* sd = (float4*)sx;
            for (int i = tid; i < CHUNK * Ix / 4; i += 512) sd[i] = xs[i];
        }
        __syncthreads();

        for (int si = 0; si < CHUNK; si++) {
            const int t  = dir ? (Tx - 1 - (s0 + si)) : (s0 + si);
            const int li = t - tbase;  // fwd: si, bwd: CHUNK-1-si

            F2U acc; acc.f = make_float2(half ? 0.0f : bias_g, 0.0f);

            const float2* xv = (const float2*)(sx + li * Ix) + half * 10;
            #pragma unroll
            for (int j = 0; j < 10; j++) { F2U u; u.f = xv[j]; ffma2(acc.u, u.u, wih[j]); }

            const float2* hv = (const float2*)sh + half * 16;
            #pragma unroll
            for (int j = 0; j < 16; j++) { F2U u; u.f = hv[j]; ffma2(acc.u, u.u, whh[j]); }

            float v = acc.f.x + acc.f.y;
            v += __shfl_xor_sync(0xffffffffu, v, 1);

            // distributed nonlinearity at the owning pair (no divergence: per-warp uniform)
            float a = (region == 2) ? ftanh_fast(v) : fsigmoid(v);
            if (half == 0) sgates[g] = a;
            __syncthreads();

            if (tid < Hx) {
                const float ig = sgates[tid];
                const float fg = sgates[Hx + tid];
                const float gg = sgates[2 * Hx + tid];
                const float og = sgates[3 * Hx + tid];
                cstate = fg * cstate + ig * gg;
                const float h = og * ftanh_fast(cstate);
                sh[tid] = h;
                hout[((size_t)b * Tx + t) * Hx + tid] = h;
            }
            __syncthreads();
        }
    }
}

// ================= MLP head kernel =================
// out[b,t] = sigmoid(b2 + sum_o W2[o] * relu(b1[o] + W1[o,:] . [hf;hb]))
// one thread per token, W1 broadcast from SMEM, h in registers, 4 f32x2 chains.
__global__ __launch_bounds__(256, 1)
void head_kernel(const float* __restrict__ W1, const float* __restrict__ b1,
                 const float* __restrict__ W2, const float* __restrict__ b2,
                 float* __restrict__ out)
{
    __shared__ __align__(16) float sW1[64 * 128];  // 32 KB
    __shared__ float sb1[64];
    __shared__ float sW2[64];
    __shared__ float sb2;

    const int tid = threadIdx.x;
    for (int i = tid; i < 64 * 128; i += 256) sW1[i] = W1[i];
    if (tid < 64) { sb1[tid] = b1[tid]; sW2[tid] = W2[tid]; }
    if (tid == 0) sb2 = b2[0];
    __syncthreads();

    const size_t tok = (size_t)blockIdx.x * 256 + tid;  // = b*T + t; grid covers exactly B*T

    // load h = [hf(64) ; hb(64)] into registers as 64 packed f32x2
    unsigned long long hreg[64];
    {
        const float2* pf = (const float2*)(g_hf + tok * Hx);
        const float2* pb = (const float2*)(g_hb + tok * Hx);
        #pragma unroll
        for (int j = 0; j < 32; j++) { F2U u; u.f = pf[j]; hreg[j] = u.u; }
        #pragma unroll
        for (int j = 0; j < 32; j++) { F2U u; u.f = pb[j]; hreg[32 + j] = u.u; }
    }

    float acc_out = sb2;
    for (int o = 0; o < 64; o++) {
        F2U a0, a1, a2, a3;
        a0.f = make_float2(sb1[o], 0.0f);
        a1.f = make_float2(0.0f, 0.0f);
        a2.f = a1.f; a3.f = a1.f;
        const ulonglong2* w = (const ulonglong2*)(sW1 + o * 128);  // 16B LDS, broadcast
        #pragma unroll
        for (int j = 0; j < 16; j++) {
            const ulonglong2 wv0 = w[2 * j];
            const ulonglong2 wv1 = w[2 * j + 1];
            ffma2(a0.u, hreg[4 * j + 0], wv0.x);
            ffma2(a1.u, hreg[4 * j + 1], wv0.y);
            ffma2(a2.u, hreg[4 * j + 2], wv1.x);
            ffma2(a3.u, hreg[4 * j + 3], wv1.y);
        }
        float z = (a0.f.x + a0.f.y) + (a1.f.x + a1.f.y)
                + (a2.f.x + a2.f.y) + (a3.f.x + a3.f.y);
        z = fmaxf(z, 0.0f);
        acc_out = fmaf(z, sW2[o], acc_out);
    }
    out[tok] = fsigmoid(acc_out);
}

// ================= launch =================
extern "C" void kernel_launch(void* const* d_in, const int* in_sizes, int n_in,
                              void* d_out, int out_size)
{
    const float* x     = (const float*)d_in[0];
    const float* Wih_f = (const float*)d_in[1];
    const float* Whh_f = (const float*)d_in[2];
    const float* bih_f = (const float*)d_in[3];
    const float* bhh_f = (const float*)d_in[4];
    const float* Wih_b = (const float*)d_in[5];
    const float* Whh_b = (const float*)d_in[6];
    const float* bih_b = (const float*)d_in[7];
    const float* bhh_b = (const float*)d_in[8];
    const float* W1    = (const float*)d_in[9];
    const float* b1    = (const float*)d_in[10];
    const float* W2    = (const float*)d_in[11];
    const float* b2    = (const float*)d_in[12];
    float* out = (float*)d_out;

    lstm_kernel<<<Bx * 2, 512>>>(x, Wih_f, Whh_f, bih_f, bhh_f,
                                 Wih_b, Whh_b, bih_b, bhh_b);
    head_kernel<<<(Bx * Tx) / 256, 256>>>(W1, b1, W2, b2, out);
}

// round 2
// speedup vs baseline: 1.6493x; 1.6493x over previous
#include <cuda_runtime.h>
#include <cstdint>

// Problem constants
#define Bx 256
#define Tx 3000
#define Ix 40
#define Hx 64
#define Gx 256        // 4*H gates
#define RCH 20        // recurrent x_proj chunk (3000 % 20 == 0)
#define XTK 50        // xproj tokens per block (3000 % 50 == 0)

// Scratch (allocation-free rule: __device__ globals)
__device__ float g_h[2][(size_t)Bx * Tx * Hx];    // per-direction hidden outputs
__device__ float g_xp[2][(size_t)Bx * Tx * Gx];   // input projections (+biases); dir1 time-reversed

// ---------- packed f32x2 helpers ----------
union F2U { float2 f; unsigned long long u; };

__device__ __forceinline__ void ffma2(unsigned long long& acc,
                                      unsigned long long a,
                                      unsigned long long b) {
    asm("fma.rn.f32x2 %0, %1, %2, %0;" : "+l"(acc) : "l"(a), "l"(b));
}
__device__ __forceinline__ unsigned long long fadd2(unsigned long long a, unsigned long long b) {
    unsigned long long r;
    asm("add.rn.f32x2 %0, %1, %2;" : "=l"(r) : "l"(a), "l"(b));
    return r;
}

__device__ __forceinline__ float fsigmoid(float x) {
    return __fdividef(1.0f, 1.0f + __expf(-x));
}
__device__ __forceinline__ float ftanh_fast(float x) {
    return 1.0f - __fdividef(2.0f, __expf(2.0f * x) + 1.0f);
}

// ---------- cp.async helpers ----------
__device__ __forceinline__ unsigned int smem_u32(const void* p) {
    return (unsigned int)__cvta_generic_to_shared(p);
}
__device__ __forceinline__ void cp_async16(unsigned int s, const void* g) {
    asm volatile("cp.async.cg.shared.global [%0], [%1], 16;" :: "r"(s), "l"(g));
}
#define CP_COMMIT() asm volatile("cp.async.commit_group;")
#define CP_WAIT1()  asm volatile("cp.async.wait_group 1;")

// ================= x-projection kernel =================
// xp[dir][b][s][g] = x[b,t,:] . W_ih[dir][g,:] + b_ih[g] + b_hh[g]
// where t = s for dir 0, t = T-1-s for dir 1 (time-reversed storage so the
// recurrent kernel streams both directions identically).
__global__ __launch_bounds__(256)
void xproj_kernel(const float* __restrict__ x,
                  const float* __restrict__ WihF, const float* __restrict__ bihF,
                  const float* __restrict__ bhhF,
                  const float* __restrict__ WihB, const float* __restrict__ bihB,
                  const float* __restrict__ bhhB)
{
    const int dir = blockIdx.y;
    const float* Wih = dir ? WihB : WihF;
    const int g = threadIdx.x;

    __shared__ __align__(16) float sx[XTK * Ix];

    // gate's W_ih row in registers (40 floats = 20 f32x2)
    unsigned long long w[20];
    {
        const float2* wr = (const float2*)(Wih + (size_t)g * Ix);
        #pragma unroll
        for (int j = 0; j < 20; j++) { F2U u; u.f = wr[j]; w[j] = u.u; }
    }
    const float bias = dir ? (bihB[g] + bhhB[g]) : (bihF[g] + bhhF[g]);

    const int tiles_per_b = Tx / XTK;
    const int batch = blockIdx.x / tiles_per_b;
    const int trel  = (blockIdx.x % tiles_per_b) * XTK;

    // stage x tile
    {
        const float4* xs = (const float4*)(x + ((size_t)batch * Tx + trel) * Ix);
        float4* sd = (float4*)sx;
        for (int i = threadIdx.x; i < XTK * Ix / 4; i += 256) sd[i] = xs[i];
    }
    __syncthreads();

    float* outp = g_xp[dir];
    #pragma unroll 2
    for (int k = 0; k < XTK; k++) {
        const unsigned long long* xr = (const unsigned long long*)(sx + k * Ix);
        F2U a0, a1;
        a0.f = make_float2(bias, 0.0f);
        a1.f = make_float2(0.0f, 0.0f);
        #pragma unroll
        for (int j = 0; j < 10; j++) {
            ffma2(a0.u, xr[2 * j],     w[2 * j]);
            ffma2(a1.u, xr[2 * j + 1], w[2 * j + 1]);
        }
        F2U s; s.u = fadd2(a0.u, a1.u);
        const float v = s.f.x + s.f.y;
        const int t = trel + k;
        const int sout = dir ? (Tx - 1 - t) : t;   // reversed storage for bwd
        outp[((size_t)batch * Tx + sout) * Gx + g] = v;
    }
}

// ================= recurrent LSTM kernel =================
// 512 blocks (one per (batch, direction)), 256 threads (one per gate),
// 2 blocks/SM. W_hh row in registers, x_proj streamed via cp.async chunks.
__global__ __launch_bounds__(256, 2)
void lstm_kernel(const float* __restrict__ Whh_f, const float* __restrict__ Whh_b)
{
    const int blk = blockIdx.x;        // 0..511
    const int b   = blk >> 1;
    const int dir = blk & 1;

    const float* Whh = dir ? Whh_b : Whh_f;
    float* hout = g_h[dir];
    const float* xp = g_xp[dir] + (size_t)b * Tx * Gx;

    const int g = threadIdx.x;

    __shared__ __align__(16) float sxp[2][RCH * Gx];  // 40 KB double buffer
    __shared__ __align__(16) float sh[Hx];
    __shared__ float sgates[Gx];

    // W_hh row (64 floats = 32 f32x2) in registers
    unsigned long long whh[32];
    {
        const float2* wr = (const float2*)(Whh + (size_t)g * Hx);
        #pragma unroll
        for (int j = 0; j < 32; j++) { F2U u; u.f = wr[j]; whh[j] = u.u; }
    }

    if (g < Hx) sh[g] = 0.0f;
    float c = 0.0f;
    const int region = g >> 6;   // warp-uniform: 0:i 1:f 2:g 3:o

    // prefetch chunk 0 (5 x 16B per thread)
    {
        const unsigned int sdst = smem_u32(&sxp[0][0]) + threadIdx.x * 16;
        const char* gsrc = (const char*)xp + threadIdx.x * 16;
        #pragma unroll
        for (int i = 0; i < 5; i++) cp_async16(sdst + i * 4096, gsrc + i * 4096);
        CP_COMMIT();
    }
    __syncthreads();   // sh init visible

    const int NCH = Tx / RCH;
    for (int ck = 0; ck < NCH; ck++) {
        // prefetch next chunk into the other buffer
        if (ck + 1 < NCH) {
            const unsigned int sdst = smem_u32(&sxp[(ck + 1) & 1][0]) + threadIdx.x * 16;
            const char* gsrc = (const char*)(xp + (size_t)(ck + 1) * RCH * Gx) + threadIdx.x * 16;
            #pragma unroll
            for (int i = 0; i < 5; i++) cp_async16(sdst + i * 4096, gsrc + i * 4096);
        }
        CP_COMMIT();
        CP_WAIT1();          // current chunk's group done
        __syncthreads();

        const float* xb = sxp[ck & 1];
        for (int si = 0; si < RCH; si++) {
            const float xv = xb[si * Gx + g];

            F2U a0, a1, a2, a3;
            a0.f = make_float2(xv, 0.0f);
            a1.f = make_float2(0.0f, 0.0f);
            a2 = a1; a3 = a1;

            const unsigned long long* hv = (const unsigned long long*)sh;  // broadcast
            #pragma unroll
            for (int j = 0; j < 8; j++) {
                ffma2(a0.u, hv[j],      whh[j]);
                ffma2(a1.u, hv[8 + j],  whh[8 + j]);
                ffma2(a2.u, hv[16 + j], whh[16 + j]);
                ffma2(a3.u, hv[24 + j], whh[24 + j]);
            }
            F2U s; s.u = fadd2(fadd2(a0.u, a1.u), fadd2(a2.u, a3.u));
            const float v = s.f.x + s.f.y;

            sgates[g] = (region == 2) ? ftanh_fast(v) : fsigmoid(v);
            __syncthreads();

            if (g < Hx) {
                const float ig = sgates[g];
                const float fg = sgates[Hx + g];
                const float gg = sgates[2 * Hx + g];
                const float og = sgates[3 * Hx + g];
                c = fg * c + ig * gg;
                const float h = og * ftanh_fast(c);
                sh[g] = h;
                const int srel = ck * RCH + si;
                const int t = dir ? (Tx - 1 - srel) : srel;
                hout[((size_t)b * Tx + t) * Hx + g] = h;
            }
            __syncthreads();
        }
    }
}

// ================= MLP head kernel =================
// 2 lanes per token: lane (tid&1)==0 handles hf half, ==1 handles hb half.
// 64 h-floats in regs per lane, shfl-combine per output unit.
__global__ __launch_bounds__(256, 2)
void head_kernel(const float* __restrict__ W1, const float* __restrict__ b1,
                 const float* __restrict__ W2, const float* __restrict__ b2,
                 float* __restrict__ out)
{
    __shared__ __align__(16) float sW1[64 * 128];  // 32 KB
    __shared__ float sb1[64];
    __shared__ float sW2[64];

    const int tid = threadIdx.x;
    for (int i = tid; i < 64 * 128 / 4; i += 256)
        ((float4*)sW1)[i] = ((const float4*)W1)[i];
    if (tid < 64) { sb1[tid] = b1[tid]; sW2[tid] = W2[tid]; }
    __syncthreads();
    const float bias2 = b2[0];

    const size_t tok = (size_t)blockIdx.x * 128 + (tid >> 1);
    const int hsel = tid & 1;

    // this lane's 64 h floats (hf or hb) as 32 packed regs
    unsigned long long hreg[32];
    {
        const ulonglong2* hv = (const ulonglong2*)(g_h[hsel] + tok * Hx);
        #pragma unroll
        for (int j = 0; j < 16; j++) {
            ulonglong2 u = hv[j];
            hreg[2 * j] = u.x; hreg[2 * j + 1] = u.y;
        }
    }

    float acc = bias2;
    #pragma unroll 4
    for (int o = 0; o < 64; o++) {
        const unsigned long long* w =
            (const unsigned long long*)(sW1 + o * 128 + hsel * 64);
        F2U a0, a1, a2, a3;
        a0.f = make_float2(0.0f, 0.0f);
        a1 = a0; a2 = a0; a3 = a0;
        #pragma unroll
        for (int j = 0; j < 8; j++) {
            ffma2(a0.u, hreg[j],      w[j]);
            ffma2(a1.u, hreg[8 + j],  w[8 + j]);
            ffma2(a2.u, hreg[16 + j], w[16 + j]);
            ffma2(a3.u, hreg[24 + j], w[24 + j]);
        }
        F2U s; s.u = fadd2(fadd2(a0.u, a1.u), fadd2(a2.u, a3.u));
        float v = s.f.x + s.f.y;
        v += __shfl_xor_sync(0xffffffffu, v, 1);   // combine hf/hb halves
        const float z = fmaxf(v + sb1[o], 0.0f);
        acc = fmaf(z, sW2[o], acc);
    }
    if (hsel == 0) out[tok] = fsigmoid(acc);
}

// ================= launch =================
extern "C" void kernel_launch(void* const* d_in, const int* in_sizes, int n_in,
                              void* d_out, int out_size)
{
    const float* x     = (const float*)d_in[0];
    const float* Wih_f = (const float*)d_in[1];
    const float* Whh_f = (const float*)d_in[2];
    const float* bih_f = (const float*)d_in[3];
    const float* bhh_f = (const float*)d_in[4];
    const float* Wih_b = (const float*)d_in[5];
    const float* Whh_b = (const float*)d_in[6];
    const float* bih_b = (const float*)d_in[7];
    const float* bhh_b = (const float*)d_in[8];
    const float* W1    = (const float*)d_in[9];
    const float* b1    = (const float*)d_in[10];
    const float* W2    = (const float*)d_in[11];
    const float* b2    = (const float*)d_in[12];
    float* out = (float*)d_out;

    dim3 gx(Bx * (Tx / XTK), 2);
    xproj_kernel<<<gx, 256>>>(x, Wih_f, bih_f, bhh_f, Wih_b, bih_b, bhh_b);
    lstm_kernel<<<Bx * 2, 256>>>(Whh_f, Whh_b);
    head_kernel<<<(Bx * Tx) / 128, 256>>>(W1, b1, W2, b2, out);
}

// round 3
// speedup vs baseline: 1.9133x; 1.1601x over previous
#include <cuda_runtime.h>
#include <cstdint>

// Problem constants
#define Bx 256
#define Tx 3000
#define Ix 40
#define Hx 64
#define Gx 256        // 4*H gates
#define RCH 8         // recurrent x_proj chunk steps (3000 % 8 == 0 -> 375 chunks)
#define XTK 50        // xproj tokens per block (3000 % 50 == 0)

// Scratch (allocation-free rule: __device__ globals)
__device__ float g_h[2][(size_t)Bx * Tx * Hx];    // per-direction hidden outputs
__device__ float g_xp[2][(size_t)Bx * Tx * Gx];   // input projections (+biases); dir1 time-reversed

// ---------- packed f32x2 helpers ----------
union F2U { float2 f; unsigned long long u; };

__device__ __forceinline__ void ffma2(unsigned long long& acc,
                                      unsigned long long a,
                                      unsigned long long b) {
    asm("fma.rn.f32x2 %0, %1, %2, %0;" : "+l"(acc) : "l"(a), "l"(b));
}
__device__ __forceinline__ unsigned long long fadd2(unsigned long long a, unsigned long long b) {
    unsigned long long r;
    asm("add.rn.f32x2 %0, %1, %2;" : "=l"(r) : "l"(a), "l"(b));
    return r;
}
__device__ __forceinline__ float fsigmoid(float x) {
    return __fdividef(1.0f, 1.0f + __expf(-x));
}
__device__ __forceinline__ float ftanh_fast(float x) {
    return 1.0f - __fdividef(2.0f, __expf(2.0f * x) + 1.0f);
}

// ---------- cp.async helpers ----------
__device__ __forceinline__ unsigned int smem_u32(const void* p) {
    return (unsigned int)__cvta_generic_to_shared(p);
}
__device__ __forceinline__ void cp_async16(unsigned int s, const void* g) {
    asm volatile("cp.async.cg.shared.global [%0], [%1], 16;" :: "r"(s), "l"(g));
}
#define CP_COMMIT() asm volatile("cp.async.commit_group;")
#define CP_WAIT1()  asm volatile("cp.async.wait_group 1;")

// ================= x-projection kernel =================
// Both directions per block: thread g holds W_ih rows for dir0 and dir1,
// x tile read once from SMEM as LDS.128 broadcasts.
// dir1 output stored time-reversed so the recurrent kernel streams forward.
__global__ __launch_bounds__(256)
void xproj_kernel(const float* __restrict__ x,
                  const float* __restrict__ WihF, const float* __restrict__ bihF,
                  const float* __restrict__ bhhF,
                  const float* __restrict__ WihB, const float* __restrict__ bihB,
                  const float* __restrict__ bhhB)
{
    const int g = threadIdx.x;
    __shared__ __align__(16) float sx[XTK * Ix];   // 8 KB

    unsigned long long wf[20], wb[20];
    {
        const float2* wrf = (const float2*)(WihF + (size_t)g * Ix);
        const float2* wrb = (const float2*)(WihB + (size_t)g * Ix);
        #pragma unroll
        for (int j = 0; j < 20; j++) { F2U u; u.f = wrf[j]; wf[j] = u.u; }
        #pragma unroll
        for (int j = 0; j < 20; j++) { F2U u; u.f = wrb[j]; wb[j] = u.u; }
    }
    const float biasF = bihF[g] + bhhF[g];
    const float biasB = bihB[g] + bhhB[g];

    const int tiles_per_b = Tx / XTK;
    const int batch = blockIdx.x / tiles_per_b;
    const int trel  = (blockIdx.x % tiles_per_b) * XTK;

    {
        const float4* xs = (const float4*)(x + ((size_t)batch * Tx + trel) * Ix);
        float4* sd = (float4*)sx;
        #pragma unroll
        for (int i = 0; i < XTK * Ix / 4 / 256 + 1; i++) {
            int idx = threadIdx.x + i * 256;
            if (idx < XTK * Ix / 4) sd[idx] = xs[idx];
        }
    }
    __syncthreads();

    float* outF = g_xp[0];
    float* outB = g_xp[1];
    for (int k = 0; k < XTK; k++) {
        const ulonglong2* xr = (const ulonglong2*)(sx + k * Ix);
        F2U f0, f1, b0, b1;
        f0.f = make_float2(biasF, 0.0f);
        f1.f = make_float2(0.0f, 0.0f);
        b0.f = make_float2(biasB, 0.0f);
        b1.f = make_float2(0.0f, 0.0f);
        #pragma unroll
        for (int j = 0; j < 10; j++) {
            const ulonglong2 u = xr[j];          // LDS.128 broadcast
            ffma2(f0.u, u.x, wf[2 * j]);
            ffma2(f1.u, u.y, wf[2 * j + 1]);
            ffma2(b0.u, u.x, wb[2 * j]);
            ffma2(b1.u, u.y, wb[2 * j + 1]);
        }
        F2U sf; sf.u = fadd2(f0.u, f1.u);
        F2U sb; sb.u = fadd2(b0.u, b1.u);
        const int t = trel + k;
        outF[((size_t)batch * Tx + t) * Gx + g] = sf.f.x + sf.f.y;
        outB[((size_t)batch * Tx + (Tx - 1 - t)) * Gx + g] = sb.f.x + sb.f.y;
    }
}

// ================= recurrent LSTM kernel =================
// 256 blocks; block handles 2 sequences (batches 2p, 2p+1) of one direction.
// Thread g: gate g for BOTH sequences (shared W_hh row in regs). Single wave.
__global__ __launch_bounds__(256, 2)
void lstm_kernel(const float* __restrict__ Whh_f, const float* __restrict__ Whh_b)
{
    const int dir   = blockIdx.x & 1;
    const int bpair = blockIdx.x >> 1;          // 0..127
    const int bA    = 2 * bpair;

    const float* Whh = dir ? Whh_b : Whh_f;
    float* hout = g_h[dir];
    const float* xpA = g_xp[dir] + (size_t)bA * Tx * Gx;
    const float* xpB = xpA + (size_t)Tx * Gx;

    const int g = threadIdx.x;

    __shared__ __align__(16) float sxp[2][2][RCH * Gx];  // [seq][buf] 32 KB
    __shared__ __align__(16) float sh[2][Hx];
    __shared__ float sgates[2][Gx];

    // W_hh row (64 floats = 32 f32x2) in registers, shared by both sequences
    unsigned long long whh[32];
    {
        const float2* wr = (const float2*)(Whh + (size_t)g * Hx);
        #pragma unroll
        for (int j = 0; j < 32; j++) { F2U u; u.f = wr[j]; whh[j] = u.u; }
    }

    if (g < 128) sh[g >> 6][g & 63] = 0.0f;
    float c = 0.0f;                       // c for (seq=(g>>6)&1, idx=g&63), 2x redundant
    const int region = g >> 6;            // warp-uniform gate type
    const int us  = (g >> 6) & 1;         // update seq
    const int uix = g & 63;               // update h index

    const int SEG = RCH * Gx * 4 / 16;    // 512 16B segments per seq-chunk
    // prefetch chunk 0 for both seqs (2 segs per thread per seq)
    {
        unsigned int sA = smem_u32(&sxp[0][0][0]) + threadIdx.x * 16;
        unsigned int sB = smem_u32(&sxp[1][0][0]) + threadIdx.x * 16;
        const char* gA = (const char*)xpA + threadIdx.x * 16;
        const char* gB = (const char*)xpB + threadIdx.x * 16;
        cp_async16(sA, gA); cp_async16(sA + 4096, gA + 4096);
        cp_async16(sB, gB); cp_async16(sB + 4096, gB + 4096);
        CP_COMMIT();
    }
    __syncthreads();

    const int NCH = Tx / RCH;
    for (int ck = 0; ck < NCH; ck++) {
        if (ck + 1 < NCH) {
            const int nb = (ck + 1) & 1;
            unsigned int sA = smem_u32(&sxp[0][nb][0]) + threadIdx.x * 16;
            unsigned int sB = smem_u32(&sxp[1][nb][0]) + threadIdx.x * 16;
            const char* gA = (const char*)(xpA + (size_t)(ck + 1) * RCH * Gx) + threadIdx.x * 16;
            const char* gB = (const char*)(xpB + (size_t)(ck + 1) * RCH * Gx) + threadIdx.x * 16;
            cp_async16(sA, gA); cp_async16(sA + 4096, gA + 4096);
            cp_async16(sB, gB); cp_async16(sB + 4096, gB + 4096);
        }
        CP_COMMIT();
        CP_WAIT1();
        __syncthreads();

        const int cb = ck & 1;
        const float* xbA = sxp[0][cb];
        const float* xbB = sxp[1][cb];

        for (int si = 0; si < RCH; si++) {
            const float xvA = xbA[si * Gx + g];
            const float xvB = xbB[si * Gx + g];

            F2U aA0, aA1, aB0, aB1;
            aA0.f = make_float2(xvA, 0.0f);
            aB0.f = make_float2(xvB, 0.0f);
            aA1.f = make_float2(0.0f, 0.0f);
            aB1.f = aA1.f;

            const ulonglong2* hA = (const ulonglong2*)sh[0];  // LDS.128 broadcast
            const ulonglong2* hB = (const ulonglong2*)sh[1];
            #pragma unroll
            for (int j = 0; j < 16; j++) {
                const ulonglong2 ua = hA[j];
                const ulonglong2 ub = hB[j];
                ffma2(aA0.u, ua.x, whh[2 * j]);
                ffma2(aA1.u, ua.y, whh[2 * j + 1]);
                ffma2(aB0.u, ub.x, whh[2 * j]);
                ffma2(aB1.u, ub.y, whh[2 * j + 1]);
            }
            F2U sA; sA.u = fadd2(aA0.u, aA1.u);
            F2U sB; sB.u = fadd2(aB0.u, aB1.u);
            const float vA = sA.f.x + sA.f.y;
            const float vB = sB.f.x + sB.f.y;

            if (region == 2) {
                sgates[0][g] = ftanh_fast(vA);
                sgates[1][g] = ftanh_fast(vB);
            } else {
                sgates[0][g] = fsigmoid(vA);
                sgates[1][g] = fsigmoid(vB);
            }
            __syncthreads();

            // all 256 threads update (2x redundant per (seq,idx); benign same-value race)
            {
                const float ig = sgates[us][uix];
                const float fg = sgates[us][64 + uix];
                const float gg = sgates[us][128 + uix];
                const float og = sgates[us][192 + uix];
                c = fg * c + ig * gg;
                const float h = og * ftanh_fast(c);
                sh[us][uix] = h;
                if (g < 128) {
                    const int srel = ck * RCH + si;
                    const int t = dir ? (Tx - 1 - srel) : srel;
                    hout[((size_t)(bA + us) * Tx + t) * Hx + uix] = h;
                }
            }
            __syncthreads();
        }
    }
}

// ================= MLP head kernel =================
// 2 lanes per token (hf/hb halves), shfl-combine per output unit.
__global__ __launch_bounds__(256, 2)
void head_kernel(const float* __restrict__ W1, const float* __restrict__ b1,
                 const float* __restrict__ W2, const float* __restrict__ b2,
                 float* __restrict__ out)
{
    __shared__ __align__(16) float sW1[64 * 128];  // 32 KB
    __shared__ float sb1[64];
    __shared__ float sW2[64];

    const int tid = threadIdx.x;
    for (int i = tid; i < 64 * 128 / 4; i += 256)
        ((float4*)sW1)[i] = ((const float4*)W1)[i];
    if (tid < 64) { sb1[tid] = b1[tid]; sW2[tid] = W2[tid]; }
    __syncthreads();
    const float bias2 = b2[0];

    const size_t tok = (size_t)blockIdx.x * 128 + (tid >> 1);
    const int hsel = tid & 1;

    unsigned long long hreg[32];
    {
        const ulonglong2* hv = (const ulonglong2*)(g_h[hsel] + tok * Hx);
        #pragma unroll
        for (int j = 0; j < 16; j++) {
            ulonglong2 u = hv[j];
            hreg[2 * j] = u.x; hreg[2 * j + 1] = u.y;
        }
    }

    float acc = bias2;
    #pragma unroll 4
    for (int o = 0; o < 64; o++) {
        const unsigned long long* w =
            (const unsigned long long*)(sW1 + o * 128 + hsel * 64);
        F2U a0, a1, a2, a3;
        a0.f = make_float2(0.0f, 0.0f);
        a1 = a0; a2 = a0; a3 = a0;
        #pragma unroll
        for (int j = 0; j < 8; j++) {
            ffma2(a0.u, hreg[j],      w[j]);
            ffma2(a1.u, hreg[8 + j],  w[8 + j]);
            ffma2(a2.u, hreg[16 + j], w[16 + j]);
            ffma2(a3.u, hreg[24 + j], w[24 + j]);
        }
        F2U s; s.u = fadd2(fadd2(a0.u, a1.u), fadd2(a2.u, a3.u));
        float v = s.f.x + s.f.y;
        v += __shfl_xor_sync(0xffffffffu, v, 1);
        const float z = fmaxf(v + sb1[o], 0.0f);
        acc = fmaf(z, sW2[o], acc);
    }
    if (hsel == 0) out[tok] = fsigmoid(acc);
}

// ================= launch =================
extern "C" void kernel_launch(void* const* d_in, const int* in_sizes, int n_in,
                              void* d_out, int out_size)
{
    const float* x     = (const float*)d_in[0];
    const float* Wih_f = (const float*)d_in[1];
    const float* Whh_f = (const float*)d_in[2];
    const float* bih_f = (const float*)d_in[3];
    const float* bhh_f = (const float*)d_in[4];
    const float* Wih_b = (const float*)d_in[5];
    const float* Whh_b = (const float*)d_in[6];
    const float* bih_b = (const float*)d_in[7];
    const float* bhh_b = (const float*)d_in[8];
    const float* W1    = (const float*)d_in[9];
    const float* b1    = (const float*)d_in[10];
    const float* W2    = (const float*)d_in[11];
    const float* b2    = (const float*)d_in[12];
    float* out = (float*)d_out;

    xproj_kernel<<<Bx * (Tx / XTK), 256>>>(x, Wih_f, bih_f, bhh_f, Wih_b, bih_b, bhh_b);
    lstm_kernel<<<Bx, 256>>>(Whh_f, Whh_b);   // 256 blocks, 2 sequences each
    head_kernel<<<(Bx * Tx) / 128, 256>>>(W1, b1, W2, b2, out);
}